// round 6
// baseline (speedup 1.0000x reference)
#include <cuda_runtime.h>
#include <cuda_bf16.h>
#include <cstdint>

#define NB 16
#define LL 512
#define EE 256
#define FF 256
#define MM 4096
#define OUT_ELEMS (NB * MM * EE)   // 16777216
#define KTOT 768
#define NROWS (NB * LL)            // 8192
#define KC 32                      // K chunk (bf16) = 64 B rows
#define NCHUNK (KTOT / KC)         // 24
#define NSTAGE 4
#define ROWB 80                    // padded row bytes (64 data + 16 pad) -> 20 words

// ---------------- scratch (hi/lo bf16 planes for 3xBF16 compensation) --------
__device__ __nv_bfloat16 g_xh1[NROWS * KTOT];  // im2col(x) hi
__device__ __nv_bfloat16 g_xl1[NROWS * KTOT];  // im2col(x) lo
__device__ __nv_bfloat16 g_xh2[NROWS * KTOT];  // im2col(h1) hi  (halo rows stay 0)
__device__ __nv_bfloat16 g_xl2[NROWS * KTOT];  // im2col(h1) lo
__device__ __nv_bfloat16 g_wh1[FF * KTOT];
__device__ __nv_bfloat16 g_wl1[FF * KTOT];
__device__ __nv_bfloat16 g_wh2[FF * KTOT];
__device__ __nv_bfloat16 g_wl2[FF * KTOT];
__device__ int           g_idx[NB * MM];

// ---------------- smem layout ----------------
#define ASZ   (128 * ROWB)             // 10240: A_hi rows 0-63, A_lo rows 64-127
#define BSZ   (512 * ROWB)             // 40960: B_hi rows 0-255, B_lo rows 256-511
#define STAGE (ASZ + BSZ)              // 51200
#define SM_PAR (NSTAGE * STAGE)        // 204800: bias|gamma|beta|lw
#define SM_TOTAL (SM_PAR + 4096)       // 208896

// ---------------- helpers ----------------
__device__ __forceinline__ uint32_t smem_u32(const void* p) {
    uint32_t a;
    asm("{ .reg .u64 t; cvta.to.shared.u64 t, %1; cvt.u32.u64 %0, t; }" : "=r"(a) : "l"(p));
    return a;
}
__device__ __forceinline__ void cp16(uint32_t dst, const void* src) {
    asm volatile("cp.async.cg.shared.global [%0], [%1], 16;" :: "r"(dst), "l"(src));
}
#define CP_COMMIT() asm volatile("cp.async.commit_group;" ::: "memory")
template <int N>
__device__ __forceinline__ void cp_wait() {
    asm volatile("cp.async.wait_group %0;" :: "n"(N) : "memory");
}
__device__ __forceinline__ uint32_t lds32(uint32_t a) {
    uint32_t v;
    asm volatile("ld.shared.b32 %0, [%1];" : "=r"(v) : "r"(a));
    return v;
}
__device__ __forceinline__ void mma_bf16(float* d, uint32_t a0, uint32_t a1,
                                         uint32_t a2, uint32_t a3,
                                         uint32_t b0, uint32_t b1) {
    asm volatile(
        "mma.sync.aligned.m16n8k16.row.col.f32.bf16.bf16.f32 "
        "{%0,%1,%2,%3}, {%4,%5,%6,%7}, {%8,%9}, {%0,%1,%2,%3};"
        : "+f"(d[0]), "+f"(d[1]), "+f"(d[2]), "+f"(d[3])
        : "r"(a0), "r"(a1), "r"(a2), "r"(a3), "r"(b0), "r"(b1));
}
__device__ __forceinline__ void split_bf16(float v, __nv_bfloat16& hi, __nv_bfloat16& lo) {
    hi = __float2bfloat16(v);
    lo = __float2bfloat16(v - __bfloat162float(hi));
}

// ---------------- weight prep: w[f][e][k] fp32 -> hi/lo [f][k*256+e] ---------
__global__ void prep_w_kernel(const float* __restrict__ w1, const float* __restrict__ w2) {
    int f = blockIdx.x;
    const float* w = blockIdx.y ? w2 : w1;
    __nv_bfloat16* wh = blockIdx.y ? g_wh2 : g_wh1;
    __nv_bfloat16* wl = blockIdx.y ? g_wl2 : g_wl1;
    int e = threadIdx.x;
#pragma unroll
    for (int k = 0; k < 3; ++k) {
        __nv_bfloat16 hi, lo;
        split_bf16(w[f * KTOT + e * 3 + k], hi, lo);
        wh[f * KTOT + k * 256 + e] = hi;
        wl[f * KTOT + k * 256 + e] = lo;
    }
}

// ---------------- im2col of x: fp32 -> hi/lo planes [row][k*256+e] -----------
__global__ void __launch_bounds__(256) im2col_kernel(const float* __restrict__ x) {
    int warp = threadIdx.x >> 5, lane = threadIdx.x & 31;
    int row = blockIdx.x * 8 + warp;
    int n = row >> 9, l = row & 511;
    int e0 = lane * 8;
#pragma unroll
    for (int k = 0; k < 3; ++k) {
        int sl = l + k - 1;
        uint4 vh = make_uint4(0u, 0u, 0u, 0u), vl = vh;
        if (sl >= 0 && sl < LL) {
            const float* xr = x + ((size_t)(n * LL + sl) * EE + e0);
            uint32_t* ph = reinterpret_cast<uint32_t*>(&vh);
            uint32_t* pl = reinterpret_cast<uint32_t*>(&vl);
#pragma unroll
            for (int q = 0; q < 4; ++q) {
                __nv_bfloat16 h0, l0, h1, l1;
                split_bf16(xr[2 * q], h0, l0);
                split_bf16(xr[2 * q + 1], h1, l1);
                ph[q] = ((uint32_t)*reinterpret_cast<uint16_t*>(&h1) << 16) |
                        *reinterpret_cast<uint16_t*>(&h0);
                pl[q] = ((uint32_t)*reinterpret_cast<uint16_t*>(&l1) << 16) |
                        *reinterpret_cast<uint16_t*>(&l0);
            }
        }
        size_t doff = (size_t)row * KTOT + k * 256 + e0;
        *reinterpret_cast<uint4*>(g_xh1 + doff) = vh;
        *reinterpret_cast<uint4*>(g_xl1 + doff) = vl;
    }
}

// ---------------- build idx map ----------------
__global__ void build_idx_kernel(const int* __restrict__ target) {
    int n = blockIdx.x, t = threadIdx.x;
    __shared__ int s[512];
    int d = target[n * LL + t];
    s[t] = d;
    __syncthreads();
    for (int off = 1; off < 512; off <<= 1) {
        int v = (t >= off) ? s[t - off] : 0;
        __syncthreads();
        s[t] += v;
        __syncthreads();
    }
    int cum = s[t], start = cum - d;
    for (int i = t; i < MM; i += 512) g_idx[n * MM + i] = -1;
    __syncthreads();
    for (int u = start; u < cum; ++u) g_idx[n * MM + u] = t;
}

// ---------------- gather ----------------
__global__ void gather_kernel(const float* __restrict__ x, float* __restrict__ out) {
    int warp = threadIdx.x >> 5, lane = threadIdx.x & 31;
    int row = blockIdx.x * 8 + warp;
    int n = row >> 12;
    int j = g_idx[row];
    float4 v0 = make_float4(0.f, 0.f, 0.f, 0.f), v1 = v0;
    if (j >= 0) {
        const float4* src = reinterpret_cast<const float4*>(x + (size_t)(n * LL + j) * EE);
        v0 = src[lane * 2];
        v1 = src[lane * 2 + 1];
    }
    float4* dst = reinterpret_cast<float4*>(out + (size_t)row * EE);
    dst[lane * 2] = v0;
    dst[lane * 2 + 1] = v1;
}

// ---------------- 3xBF16 HMMA GEMM + fused LN/ReLU epilogue ------------------
// Y[8192,256] = X'[8192,768] @ Wb^T, compensated bf16 (fp32-grade).
// CTA: M=64, N=256; 8 warps (2m x 4n), warp tile 32x64.
// KC=32 chunks, 4-stage cp.async pipeline (prefetch depth 3).
// SECOND=0 epilogue scatters LN output directly into g_x2's 3 k-slots (fused im2col).
template <int SECOND>
__global__ void __launch_bounds__(256) gemm_ln_kernel(
    const float* __restrict__ bias, const float* __restrict__ gamma,
    const float* __restrict__ beta, const float* __restrict__ lw,
    const float* __restrict__ lbp, float* __restrict__ durout)
{
    extern __shared__ char smem[];
    uint32_t sb = smem_u32(smem);
    int tid = threadIdx.x, wid = tid >> 5, lane = tid & 31;
    int m0 = blockIdx.x * 64;
    int wm = wid & 1, wn = wid >> 1;
    int g = lane >> 2, t = lane & 3;
    const __nv_bfloat16* Ah = SECOND ? g_xh2 : g_xh1;
    const __nv_bfloat16* Al = SECOND ? g_xl2 : g_xl1;
    const __nv_bfloat16* Bh = SECOND ? g_wh2 : g_wh1;
    const __nv_bfloat16* Bl = SECOND ? g_wl2 : g_wl1;

    {
        float* pp = reinterpret_cast<float*>(smem + SM_PAR);
        pp[tid] = bias[tid];
        pp[256 + tid] = gamma[tid];
        pp[512 + tid] = beta[tid];
        pp[768 + tid] = SECOND ? lw[tid] : 0.f;
    }

    auto issue_chunk = [&](int c, int buf) {
        uint32_t sa = sb + buf * STAGE;
        uint32_t sbm = sa + ASZ;
        size_t aoff = ((size_t)m0 * KTOT + c * KC) * 2;
        size_t boff = (size_t)c * KC * 2;
        const char* gAh = reinterpret_cast<const char*>(Ah) + aoff;
        const char* gAl = reinterpret_cast<const char*>(Al) + aoff;
        const char* gBh = reinterpret_cast<const char*>(Bh) + boff;
        const char* gBl = reinterpret_cast<const char*>(Bl) + boff;
        {   // A: 64 rows x 4 segs per plane = 256 cp16 each
            int row = tid >> 2, seg = tid & 3;
            cp16(sa + row * ROWB + seg * 16, gAh + (size_t)row * 1536 + seg * 16);
            cp16(sa + (64 + row) * ROWB + seg * 16, gAl + (size_t)row * 1536 + seg * 16);
        }
#pragma unroll
        for (int i = 0; i < 4; ++i) {   // B_hi: 256 rows x 4 segs
            int lin = tid + (i << 8);
            int row = lin >> 2, seg = lin & 3;
            cp16(sbm + row * ROWB + seg * 16, gBh + (size_t)row * 1536 + seg * 16);
        }
#pragma unroll
        for (int i = 0; i < 4; ++i) {   // B_lo -> smem rows 256..511
            int lin = tid + (i << 8);
            int row = lin >> 2, seg = lin & 3;
            cp16(sbm + (256 + row) * ROWB + seg * 16, gBl + (size_t)row * 1536 + seg * 16);
        }
        CP_COMMIT();
    };

    float acc[2][8][4];
#pragma unroll
    for (int mt = 0; mt < 2; ++mt)
#pragma unroll
        for (int nt = 0; nt < 8; ++nt)
#pragma unroll
            for (int q = 0; q < 4; ++q) acc[mt][nt][q] = 0.f;

    issue_chunk(0, 0);
    issue_chunk(1, 1);
    issue_chunk(2, 2);

    for (int c = 0; c < NCHUNK; ++c) {
        int buf = c & (NSTAGE - 1);
        if (c + 3 < NCHUNK) {
            issue_chunk(c + 3, (c + 3) & (NSTAGE - 1));
            cp_wait<3>();
        } else if (c + 2 < NCHUNK) {
            cp_wait<2>();
        } else if (c + 1 < NCHUNK) {
            cp_wait<1>();
        } else {
            cp_wait<0>();
        }
        __syncthreads();
        uint32_t abase = sb + buf * STAGE;
        uint32_t bbase = abase + ASZ;
#pragma unroll
        for (int ks = 0; ks < 2; ++ks) {
            int k0 = ks * 16;
            uint32_t bh[8][2], bl[8][2];
#pragma unroll
            for (int nt = 0; nt < 8; ++nt) {
                uint32_t ba = bbase + (wn * 64 + nt * 8 + g) * ROWB + (k0 + 2 * t) * 2;
                bh[nt][0] = lds32(ba);
                bh[nt][1] = lds32(ba + 16);
                bl[nt][0] = lds32(ba + 256 * ROWB);
                bl[nt][1] = lds32(ba + 256 * ROWB + 16);
            }
#pragma unroll
            for (int mt = 0; mt < 2; ++mt) {
                uint32_t ra = abase + (wm * 32 + mt * 16 + g) * ROWB + (k0 + 2 * t) * 2;
                uint32_t ah0 = lds32(ra);
                uint32_t ah1 = lds32(ra + 8 * ROWB);
                uint32_t ah2 = lds32(ra + 16);
                uint32_t ah3 = lds32(ra + 8 * ROWB + 16);
                uint32_t la_ = ra + 64 * ROWB;
                uint32_t al0 = lds32(la_);
                uint32_t al1 = lds32(la_ + 8 * ROWB);
                uint32_t al2 = lds32(la_ + 16);
                uint32_t al3 = lds32(la_ + 8 * ROWB + 16);
#pragma unroll
                for (int nt = 0; nt < 8; ++nt) {
                    mma_bf16(acc[mt][nt], ah0, ah1, ah2, ah3, bh[nt][0], bh[nt][1]);
                    mma_bf16(acc[mt][nt], ah0, ah1, ah2, ah3, bl[nt][0], bl[nt][1]);
                    mma_bf16(acc[mt][nt], al0, al1, al2, al3, bh[nt][0], bh[nt][1]);
                }
            }
        }
        __syncthreads();
    }

    // ---------------- epilogue ----------------
    float* ot = reinterpret_cast<float*>(smem);   // [64][260] fp32, reuses stages
#pragma unroll
    for (int mt = 0; mt < 2; ++mt)
#pragma unroll
        for (int nt = 0; nt < 8; ++nt) {
            int m = wm * 32 + mt * 16 + g;
            int n = wn * 64 + nt * 8 + 2 * t;
            *reinterpret_cast<float2*>(ot + m * 260 + n) =
                make_float2(acc[mt][nt][0], acc[mt][nt][1]);
            *reinterpret_cast<float2*>(ot + (m + 8) * 260 + n) =
                make_float2(acc[mt][nt][2], acc[mt][nt][3]);
        }
    __syncthreads();

    if (tid < 64) {
        const float* pb = reinterpret_cast<const float*>(smem + SM_PAR);
        const float* pg = pb + 256;
        const float* pe = pb + 512;
        const float* pl = pb + 768;
        const float* rowp = ot + tid * 260;
        float h[256];
        float s = 0.f, ss = 0.f;
#pragma unroll 4
        for (int j = 0; j < 256; j += 4) {
            float4 v4 = *reinterpret_cast<const float4*>(rowp + j);
            h[j]     = v4.x + pb[j];
            h[j + 1] = v4.y + pb[j + 1];
            h[j + 2] = v4.z + pb[j + 2];
            h[j + 3] = v4.w + pb[j + 3];
            s += h[j] + h[j + 1] + h[j + 2] + h[j + 3];
            ss += h[j] * h[j] + h[j + 1] * h[j + 1] +
                  h[j + 2] * h[j + 2] + h[j + 3] * h[j + 3];
        }
        float mu = s * (1.f / 256.f);
        float var = ss * (1.f / 256.f) - mu * mu;
        float rs = rsqrtf(var + 1e-5f);
        int row = m0 + tid;
        if (!SECOND) {
            // fused im2col: scatter LN output (hi/lo) into g_x2's 3 k-slots
            int l = row & 511;
            __nv_bfloat16* xh = g_xh2;
            __nv_bfloat16* xl = g_xl2;
#pragma unroll 2
            for (int j = 0; j < 256; j += 8) {
                uint32_t wh[4], wl[4];
#pragma unroll
                for (int q = 0; q < 4; ++q) {
                    float y0 = fmaxf(0.f, (h[j + 2 * q] - mu) * rs * pg[j + 2 * q] + pe[j + 2 * q]);
                    float y1 = fmaxf(0.f, (h[j + 2 * q + 1] - mu) * rs * pg[j + 2 * q + 1] + pe[j + 2 * q + 1]);
                    __nv_bfloat16 h0, l0, h1, l1;
                    split_bf16(y0, h0, l0);
                    split_bf16(y1, h1, l1);
                    wh[q] = ((uint32_t)*reinterpret_cast<uint16_t*>(&h1) << 16) |
                            *reinterpret_cast<uint16_t*>(&h0);
                    wl[q] = ((uint32_t)*reinterpret_cast<uint16_t*>(&l1) << 16) |
                            *reinterpret_cast<uint16_t*>(&l0);
                }
                uint4 vh = make_uint4(wh[0], wh[1], wh[2], wh[3]);
                uint4 vl = make_uint4(wl[0], wl[1], wl[2], wl[3]);
                // k=1 slot at row (sl = l)
                *reinterpret_cast<uint4*>(xh + (size_t)row * KTOT + 256 + j) = vh;
                *reinterpret_cast<uint4*>(xl + (size_t)row * KTOT + 256 + j) = vl;
                // k=0 slot at row+1 (its sl = l)
                if (l < 511) {
                    *reinterpret_cast<uint4*>(xh + (size_t)(row + 1) * KTOT + j) = vh;
                    *reinterpret_cast<uint4*>(xl + (size_t)(row + 1) * KTOT + j) = vl;
                }
                // k=2 slot at row-1 (its sl = l)
                if (l > 0) {
                    *reinterpret_cast<uint4*>(xh + (size_t)(row - 1) * KTOT + 512 + j) = vh;
                    *reinterpret_cast<uint4*>(xl + (size_t)(row - 1) * KTOT + 512 + j) = vl;
                }
            }
        } else {
            float dacc = 0.f;
#pragma unroll 4
            for (int j = 0; j < 256; ++j) {
                float y = fmaxf(0.f, (h[j] - mu) * rs * pg[j] + pe[j]);
                dacc += y * pl[j];
            }
            durout[row] = fmaxf(0.f, dacc + *lbp);
        }
    }
}

// ---------------- launch ----------------
extern "C" void kernel_launch(void* const* d_in, const int* in_sizes, int n_in,
                              void* d_out, int out_size) {
    const float* x   = (const float*)d_in[0];
    const float* c1w = (const float*)d_in[1];
    const float* c1b = (const float*)d_in[2];
    const float* l1g = (const float*)d_in[3];
    const float* l1b = (const float*)d_in[4];
    const float* c2w = (const float*)d_in[5];
    const float* c2b = (const float*)d_in[6];
    const float* l2g = (const float*)d_in[7];
    const float* l2b = (const float*)d_in[8];
    const float* lw  = (const float*)d_in[9];
    const float* lb  = (const float*)d_in[10];
    const int* target = (const int*)d_in[11];
    float* out = (float*)d_out;

    cudaFuncSetAttribute(gemm_ln_kernel<0>, cudaFuncAttributeMaxDynamicSharedMemorySize, SM_TOTAL);
    cudaFuncSetAttribute(gemm_ln_kernel<1>, cudaFuncAttributeMaxDynamicSharedMemorySize, SM_TOTAL);

    prep_w_kernel<<<dim3(256, 2), 256>>>(c1w, c2w);
    im2col_kernel<<<NROWS / 8, 256>>>(x);
    build_idx_kernel<<<16, 512>>>(target);
    gemm_ln_kernel<0><<<128, 256, SM_TOTAL>>>(c1b, l1g, l1b, lw, lb, nullptr);
    gemm_ln_kernel<1><<<128, 256, SM_TOTAL>>>(c2b, l2g, l2b, lw, lb, out + OUT_ELEMS);
    gather_kernel<<<NB * MM / 8, 256>>>(x, out);
}

// round 7
// speedup vs baseline: 1.0734x; 1.0734x over previous
#include <cuda_runtime.h>
#include <cuda_bf16.h>
#include <cstdint>

#define NB 16
#define LL 512
#define EE 256
#define FF 256
#define MM 4096
#define OUT_ELEMS (NB * MM * EE)   // 16777216
#define KTOT 768
#define NROWS (NB * LL)            // 8192
#define KC 64                      // K chunk (bf16)
#define NCHUNK (KTOT / KC)         // 12
#define PADK 72                    // padded row length (bf16) -> 144 B
#define ROWB (PADK * 2)            // 144 bytes

// ---------------- scratch (hi/lo bf16 planes for 3xBF16 compensation) --------
__device__ __nv_bfloat16 g_xh1[NROWS * KTOT];  // im2col(x) hi
__device__ __nv_bfloat16 g_xl1[NROWS * KTOT];  // im2col(x) lo
__device__ __nv_bfloat16 g_xh2[NROWS * KTOT];  // im2col(h1) hi
__device__ __nv_bfloat16 g_xl2[NROWS * KTOT];  // im2col(h1) lo
__device__ __nv_bfloat16 g_h1h[NROWS * FF];    // conv1 out hi
__device__ __nv_bfloat16 g_h1l[NROWS * FF];    // conv1 out lo
__device__ __nv_bfloat16 g_wh1[FF * KTOT];
__device__ __nv_bfloat16 g_wl1[FF * KTOT];
__device__ __nv_bfloat16 g_wh2[FF * KTOT];
__device__ __nv_bfloat16 g_wl2[FF * KTOT];
__device__ int           g_idx[NB * MM];

// ---------------- smem layout ----------------
#define ASZ   (128 * ROWB)             // 18432: A_hi rows 0-63, A_lo rows 64-127
#define BSZ   (512 * ROWB)             // 73728: B_hi rows 0-255, B_lo rows 256-511
#define STAGE (ASZ + BSZ)              // 92160
#define SM_PAR (2 * STAGE)             // 184320: bias|gamma|beta|lw
#define SM_TOTAL (SM_PAR + 4096)       // 188416

// ---------------- helpers ----------------
__device__ __forceinline__ uint32_t smem_u32(const void* p) {
    uint32_t a;
    asm("{ .reg .u64 t; cvta.to.shared.u64 t, %1; cvt.u32.u64 %0, t; }" : "=r"(a) : "l"(p));
    return a;
}
__device__ __forceinline__ void cp16(uint32_t dst, const void* src) {
    asm volatile("cp.async.cg.shared.global [%0], [%1], 16;" :: "r"(dst), "l"(src));
}
#define CP_COMMIT() asm volatile("cp.async.commit_group;" ::: "memory")
template <int N>
__device__ __forceinline__ void cp_wait() {
    asm volatile("cp.async.wait_group %0;" :: "n"(N) : "memory");
}
__device__ __forceinline__ uint32_t lds32(uint32_t a) {
    uint32_t v;
    asm volatile("ld.shared.b32 %0, [%1];" : "=r"(v) : "r"(a));
    return v;
}
__device__ __forceinline__ void mma_bf16(float* d, uint32_t a0, uint32_t a1,
                                         uint32_t a2, uint32_t a3,
                                         uint32_t b0, uint32_t b1) {
    asm volatile(
        "mma.sync.aligned.m16n8k16.row.col.f32.bf16.bf16.f32 "
        "{%0,%1,%2,%3}, {%4,%5,%6,%7}, {%8,%9}, {%0,%1,%2,%3};"
        : "+f"(d[0]), "+f"(d[1]), "+f"(d[2]), "+f"(d[3])
        : "r"(a0), "r"(a1), "r"(a2), "r"(a3), "r"(b0), "r"(b1));
}
__device__ __forceinline__ void split_bf16(float v, __nv_bfloat16& hi, __nv_bfloat16& lo) {
    hi = __float2bfloat16(v);
    lo = __float2bfloat16(v - __bfloat162float(hi));
}

// ---------------- weight prep: w[f][e][k] fp32 -> hi/lo [f][k*256+e] ---------
__global__ void prep_w_kernel(const float* __restrict__ w1, const float* __restrict__ w2) {
    int f = blockIdx.x;
    const float* w = blockIdx.y ? w2 : w1;
    __nv_bfloat16* wh = blockIdx.y ? g_wh2 : g_wh1;
    __nv_bfloat16* wl = blockIdx.y ? g_wl2 : g_wl1;
    int e = threadIdx.x;
#pragma unroll
    for (int k = 0; k < 3; ++k) {
        __nv_bfloat16 hi, lo;
        split_bf16(w[f * KTOT + e * 3 + k], hi, lo);
        wh[f * KTOT + k * 256 + e] = hi;
        wl[f * KTOT + k * 256 + e] = lo;
    }
}

// ---------------- im2col: rows -> hi/lo planes [row][k*256+e], zero halo -----
// SRC=0: from x (fp32);  SRC=1: from g_h1h/g_h1l (bf16 planes)
template <int SRC>
__global__ void __launch_bounds__(256) im2col_kernel(const float* __restrict__ x) {
    int warp = threadIdx.x >> 5, lane = threadIdx.x & 31;
    int row = blockIdx.x * 8 + warp;
    int n = row >> 9, l = row & 511;
    int e0 = lane * 8;
    __nv_bfloat16* dh = SRC ? g_xh2 : g_xh1;
    __nv_bfloat16* dl = SRC ? g_xl2 : g_xl1;
#pragma unroll
    for (int k = 0; k < 3; ++k) {
        int sl = l + k - 1;
        uint4 vh = make_uint4(0u, 0u, 0u, 0u), vl = vh;
        if (sl >= 0 && sl < LL) {
            if (SRC == 0) {
                const float* xr = x + ((size_t)(n * LL + sl) * EE + e0);
                uint32_t* ph = reinterpret_cast<uint32_t*>(&vh);
                uint32_t* pl = reinterpret_cast<uint32_t*>(&vl);
#pragma unroll
                for (int q = 0; q < 4; ++q) {
                    __nv_bfloat16 h0, l0, h1, l1;
                    split_bf16(xr[2 * q], h0, l0);
                    split_bf16(xr[2 * q + 1], h1, l1);
                    ph[q] = ((uint32_t)*reinterpret_cast<uint16_t*>(&h1) << 16) |
                            *reinterpret_cast<uint16_t*>(&h0);
                    pl[q] = ((uint32_t)*reinterpret_cast<uint16_t*>(&l1) << 16) |
                            *reinterpret_cast<uint16_t*>(&l0);
                }
            } else {
                size_t off = (size_t)(n * LL + sl) * FF + e0;
                vh = *reinterpret_cast<const uint4*>(g_h1h + off);
                vl = *reinterpret_cast<const uint4*>(g_h1l + off);
            }
        }
        size_t doff = (size_t)row * KTOT + k * 256 + e0;
        *reinterpret_cast<uint4*>(dh + doff) = vh;
        *reinterpret_cast<uint4*>(dl + doff) = vl;
    }
}

// ---------------- build idx map ----------------
__global__ void build_idx_kernel(const int* __restrict__ target) {
    int n = blockIdx.x, t = threadIdx.x;
    __shared__ int s[512];
    int d = target[n * LL + t];
    s[t] = d;
    __syncthreads();
    for (int off = 1; off < 512; off <<= 1) {
        int v = (t >= off) ? s[t - off] : 0;
        __syncthreads();
        s[t] += v;
        __syncthreads();
    }
    int cum = s[t], start = cum - d;
    for (int i = t; i < MM; i += 512) g_idx[n * MM + i] = -1;
    __syncthreads();
    for (int u = start; u < cum; ++u) g_idx[n * MM + u] = t;
}

// ---------------- gather ----------------
__global__ void gather_kernel(const float* __restrict__ x, float* __restrict__ out) {
    int warp = threadIdx.x >> 5, lane = threadIdx.x & 31;
    int row = blockIdx.x * 8 + warp;
    int n = row >> 12;
    int j = g_idx[row];
    float4 v0 = make_float4(0.f, 0.f, 0.f, 0.f), v1 = v0;
    if (j >= 0) {
        const float4* src = reinterpret_cast<const float4*>(x + (size_t)(n * LL + j) * EE);
        v0 = src[lane * 2];
        v1 = src[lane * 2 + 1];
    }
    float4* dst = reinterpret_cast<float4*>(out + (size_t)row * EE);
    dst[lane * 2] = v0;
    dst[lane * 2 + 1] = v1;
}

// ---------------- 3xBF16 HMMA GEMM + fused LN/ReLU epilogue ------------------
// Y[8192,256] = X'[8192,768] @ Wb^T, compensated bf16 (fp32-grade).
// CTA: M=64, N=256.  512 threads, 16 warps (4m x 4n), warp tile 16x64.
// KC=64 chunks, 2-stage cp.async double buffer.
template <int SECOND>
__global__ void __launch_bounds__(512) gemm_ln_kernel(
    const float* __restrict__ bias, const float* __restrict__ gamma,
    const float* __restrict__ beta, const float* __restrict__ lw,
    const float* __restrict__ lbp, float* __restrict__ durout)
{
    extern __shared__ char smem[];
    uint32_t sb = smem_u32(smem);
    int tid = threadIdx.x, wid = tid >> 5, lane = tid & 31;
    int m0 = blockIdx.x * 64;
    int wm = wid & 3, wn = wid >> 2;           // 4m x 4n warps
    int g = lane >> 2, t = lane & 3;
    const __nv_bfloat16* Ah = SECOND ? g_xh2 : g_xh1;
    const __nv_bfloat16* Al = SECOND ? g_xl2 : g_xl1;
    const __nv_bfloat16* Bh = SECOND ? g_wh2 : g_wh1;
    const __nv_bfloat16* Bl = SECOND ? g_wl2 : g_wl1;

    if (tid < 256) {
        float* pp = reinterpret_cast<float*>(smem + SM_PAR);
        pp[tid] = bias[tid];
        pp[256 + tid] = gamma[tid];
        pp[512 + tid] = beta[tid];
        pp[768 + tid] = SECOND ? lw[tid] : 0.f;
    }

    auto issue_chunk = [&](int c, int buf) {
        uint32_t sa = sb + buf * STAGE;
        uint32_t sbm = sa + ASZ;
        size_t aoff = ((size_t)m0 * KTOT + c * KC) * 2;
        size_t boff = (size_t)c * KC * 2;
        const char* gAh = reinterpret_cast<const char*>(Ah) + aoff;
        const char* gAl = reinterpret_cast<const char*>(Al) + aoff;
        const char* gBh = reinterpret_cast<const char*>(Bh) + boff;
        const char* gBl = reinterpret_cast<const char*>(Bl) + boff;
        {   // A: 64 rows x 8 segs per plane = 512 cp16 each (1/thread/plane)
            int row = tid >> 3, seg = tid & 7;
            cp16(sa + row * ROWB + seg * 16, gAh + (size_t)row * 1536 + seg * 16);
            cp16(sa + (64 + row) * ROWB + seg * 16, gAl + (size_t)row * 1536 + seg * 16);
        }
#pragma unroll
        for (int i = 0; i < 4; ++i) {   // B_hi: 256 rows x 8 segs = 2048 cp16
            int lin = tid + (i << 9);
            int row = lin >> 3, seg = lin & 7;
            cp16(sbm + row * ROWB + seg * 16, gBh + (size_t)row * 1536 + seg * 16);
        }
#pragma unroll
        for (int i = 0; i < 4; ++i) {   // B_lo -> smem rows 256..511
            int lin = tid + (i << 9);
            int row = lin >> 3, seg = lin & 7;
            cp16(sbm + (256 + row) * ROWB + seg * 16, gBl + (size_t)row * 1536 + seg * 16);
        }
        CP_COMMIT();
    };

    float acc[8][4];
#pragma unroll
    for (int nt = 0; nt < 8; ++nt)
#pragma unroll
        for (int q = 0; q < 4; ++q) acc[nt][q] = 0.f;

    issue_chunk(0, 0);
    for (int c = 0; c < NCHUNK; ++c) {
        int buf = c & 1;
        if (c + 1 < NCHUNK) {
            issue_chunk(c + 1, buf ^ 1);
            cp_wait<1>();
        } else {
            cp_wait<0>();
        }
        __syncthreads();
        uint32_t abase = sb + buf * STAGE;
        uint32_t bbase = abase + ASZ;
#pragma unroll
        for (int ks = 0; ks < 4; ++ks) {
            int k0 = ks * 16;
            uint32_t bh[8][2], bl[8][2];
#pragma unroll
            for (int nt = 0; nt < 8; ++nt) {
                uint32_t ba = bbase + (wn * 64 + nt * 8 + g) * ROWB + (k0 + 2 * t) * 2;
                bh[nt][0] = lds32(ba);
                bh[nt][1] = lds32(ba + 16);
                bl[nt][0] = lds32(ba + 256 * ROWB);
                bl[nt][1] = lds32(ba + 256 * ROWB + 16);
            }
            uint32_t ra = abase + (wm * 16 + g) * ROWB + (k0 + 2 * t) * 2;
            uint32_t ah0 = lds32(ra);
            uint32_t ah1 = lds32(ra + 8 * ROWB);
            uint32_t ah2 = lds32(ra + 16);
            uint32_t ah3 = lds32(ra + 8 * ROWB + 16);
            uint32_t la_ = ra + 64 * ROWB;
            uint32_t al0 = lds32(la_);
            uint32_t al1 = lds32(la_ + 8 * ROWB);
            uint32_t al2 = lds32(la_ + 16);
            uint32_t al3 = lds32(la_ + 8 * ROWB + 16);
#pragma unroll
            for (int nt = 0; nt < 8; ++nt) {
                mma_bf16(acc[nt], ah0, ah1, ah2, ah3, bh[nt][0], bh[nt][1]);
                mma_bf16(acc[nt], ah0, ah1, ah2, ah3, bl[nt][0], bl[nt][1]);
                mma_bf16(acc[nt], al0, al1, al2, al3, bh[nt][0], bh[nt][1]);
            }
        }
        __syncthreads();
    }

    // ---------------- epilogue ----------------
    float* ot = reinterpret_cast<float*>(smem);   // [64][260] fp32, reuses stages
#pragma unroll
    for (int nt = 0; nt < 8; ++nt) {
        int m = wm * 16 + g;
        int n = wn * 64 + nt * 8 + 2 * t;
        *reinterpret_cast<float2*>(ot + m * 260 + n) =
            make_float2(acc[nt][0], acc[nt][1]);
        *reinterpret_cast<float2*>(ot + (m + 8) * 260 + n) =
            make_float2(acc[nt][2], acc[nt][3]);
    }
    __syncthreads();

    if (tid < 64) {
        const float* pb = reinterpret_cast<const float*>(smem + SM_PAR);
        const float* pg = pb + 256;
        const float* pe = pb + 512;
        const float* pl = pb + 768;
        const float* rowp = ot + tid * 260;
        float h[256];
        float s = 0.f, ss = 0.f;
#pragma unroll 4
        for (int j = 0; j < 256; j += 4) {
            float4 v4 = *reinterpret_cast<const float4*>(rowp + j);
            h[j]     = v4.x + pb[j];
            h[j + 1] = v4.y + pb[j + 1];
            h[j + 2] = v4.z + pb[j + 2];
            h[j + 3] = v4.w + pb[j + 3];
            s += h[j] + h[j + 1] + h[j + 2] + h[j + 3];
            ss += h[j] * h[j] + h[j + 1] * h[j + 1] +
                  h[j + 2] * h[j + 2] + h[j + 3] * h[j + 3];
        }
        float mu = s * (1.f / 256.f);
        float var = ss * (1.f / 256.f) - mu * mu;
        float rs = rsqrtf(var + 1e-5f);
        int row = m0 + tid;
        if (!SECOND) {
            __nv_bfloat16* dh = g_h1h + (size_t)row * FF;
            __nv_bfloat16* dl = g_h1l + (size_t)row * FF;
#pragma unroll 2
            for (int j = 0; j < 256; j += 8) {
                uint32_t wh[4], wl[4];
#pragma unroll
                for (int q = 0; q < 4; ++q) {
                    float y0 = fmaxf(0.f, (h[j + 2 * q] - mu) * rs * pg[j + 2 * q] + pe[j + 2 * q]);
                    float y1 = fmaxf(0.f, (h[j + 2 * q + 1] - mu) * rs * pg[j + 2 * q + 1] + pe[j + 2 * q + 1]);
                    __nv_bfloat16 h0, l0, h1, l1;
                    split_bf16(y0, h0, l0);
                    split_bf16(y1, h1, l1);
                    wh[q] = ((uint32_t)*reinterpret_cast<uint16_t*>(&h1) << 16) |
                            *reinterpret_cast<uint16_t*>(&h0);
                    wl[q] = ((uint32_t)*reinterpret_cast<uint16_t*>(&l1) << 16) |
                            *reinterpret_cast<uint16_t*>(&l0);
                }
                *reinterpret_cast<uint4*>(dh + j) = make_uint4(wh[0], wh[1], wh[2], wh[3]);
                *reinterpret_cast<uint4*>(dl + j) = make_uint4(wl[0], wl[1], wl[2], wl[3]);
            }
        } else {
            float dacc = 0.f;
#pragma unroll 4
            for (int j = 0; j < 256; ++j) {
                float y = fmaxf(0.f, (h[j] - mu) * rs * pg[j] + pe[j]);
                dacc += y * pl[j];
            }
            durout[row] = fmaxf(0.f, dacc + *lbp);
        }
    }
}

// ---------------- launch ----------------
extern "C" void kernel_launch(void* const* d_in, const int* in_sizes, int n_in,
                              void* d_out, int out_size) {
    const float* x   = (const float*)d_in[0];
    const float* c1w = (const float*)d_in[1];
    const float* c1b = (const float*)d_in[2];
    const float* l1g = (const float*)d_in[3];
    const float* l1b = (const float*)d_in[4];
    const float* c2w = (const float*)d_in[5];
    const float* c2b = (const float*)d_in[6];
    const float* l2g = (const float*)d_in[7];
    const float* l2b = (const float*)d_in[8];
    const float* lw  = (const float*)d_in[9];
    const float* lb  = (const float*)d_in[10];
    const int* target = (const int*)d_in[11];
    float* out = (float*)d_out;

    cudaFuncSetAttribute(gemm_ln_kernel<0>, cudaFuncAttributeMaxDynamicSharedMemorySize, SM_TOTAL);
    cudaFuncSetAttribute(gemm_ln_kernel<1>, cudaFuncAttributeMaxDynamicSharedMemorySize, SM_TOTAL);

    prep_w_kernel<<<dim3(256, 2), 256>>>(c1w, c2w);
    im2col_kernel<0><<<NROWS / 8, 256>>>(x);
    build_idx_kernel<<<16, 512>>>(target);
    gemm_ln_kernel<0><<<128, 512, SM_TOTAL>>>(c1b, l1g, l1b, lw, lb, nullptr);
    im2col_kernel<1><<<NROWS / 8, 256>>>(nullptr);
    gemm_ln_kernel<1><<<128, 512, SM_TOTAL>>>(c2b, l2g, l2b, lw, lb, out + OUT_ELEMS);
    gather_kernel<<<NB * MM / 8, 256>>>(x, out);
}